// round 6
// baseline (speedup 1.0000x reference)
#include <cuda_runtime.h>
#include <cstdint>
#include <math.h>

namespace {
constexpr int B_ = 2;
constexpr int C_ = 32;
constexpr int H_ = 128;
constexpr int W_ = 160;
constexpr int D_ = 32;
constexpr int N_ = 4;
constexpr int HW_ = H_ * W_;
constexpr int CAP = 416;                      // per-warp dot-table entries (bound: npix<=385)
constexpr int SMEM_FLOATS = 8 * CAP * 8 + 256;  // 8 warp tables + attn staging
}

#define FULLMASK 0xffffffffu

__device__ float g_src_t[N_ * B_ * HW_ * C_];  // [v][b][pix][c]
__device__ float g_ref_t[B_ * HW_ * C_];       // [b][pix][c]
__device__ float g_dep_t[B_ * HW_ * D_];       // [b][pix][d]
__device__ float g_rt[B_ * N_ * 12];           // rot(9) + trans(3)

// ---------------------------------------------------------------------------
__global__ void transpose_c32(const float* __restrict__ in, float* __restrict__ out) {
    __shared__ float tile[32][33];
    const int p = blockIdx.z;
    const int hw0 = blockIdx.x * 32;
    const float* ip = in + (size_t)p * 32 * HW_;
    float* op = out + (size_t)p * HW_ * 32;
    const int tx = threadIdx.x, ty = threadIdx.y;
#pragma unroll
    for (int k = 0; k < 32; k += 8)
        tile[ty + k][tx] = ip[(size_t)(ty + k) * HW_ + hw0 + tx];
    __syncthreads();
#pragma unroll
    for (int k = 0; k < 32; k += 8)
        op[(size_t)(hw0 + ty + k) * 32 + tx] = tile[tx][ty + k];
}

// ---------------------------------------------------------------------------
__device__ void build_new(const float* pm, int b, int vv, float Mo[4][4]) {
    const float* E = pm + (((b * (N_ + 1) + vv) * 2 + 0) * 16);
    const float* K = pm + (((b * (N_ + 1) + vv) * 2 + 1) * 16);
    for (int i = 0; i < 3; i++)
        for (int j = 0; j < 4; j++)
            Mo[i][j] = K[i * 4 + 0] * E[0 + j] + K[i * 4 + 1] * E[4 + j] + K[i * 4 + 2] * E[8 + j];
    for (int j = 0; j < 4; j++) Mo[3][j] = E[12 + j];
}

__global__ void setup_proj(const float* __restrict__ pm) {
    const int t = threadIdx.x;
    if (t >= B_ * N_) return;
    const int b = t / N_, v = t % N_;
    float R[4][4], S[4][4];
    build_new(pm, b, 0, R);
    build_new(pm, b, v + 1, S);
    float M[4][8];
    for (int i = 0; i < 4; i++)
        for (int j = 0; j < 4; j++) { M[i][j] = R[i][j]; M[i][4 + j] = (i == j) ? 1.f : 0.f; }
    for (int c = 0; c < 4; c++) {
        int piv = c;
        for (int r = c + 1; r < 4; r++)
            if (fabsf(M[r][c]) > fabsf(M[piv][c])) piv = r;
        if (piv != c)
            for (int j = 0; j < 8; j++) { float tmp = M[c][j]; M[c][j] = M[piv][j]; M[piv][j] = tmp; }
        const float ip = 1.f / M[c][c];
        for (int j = 0; j < 8; j++) M[c][j] *= ip;
        for (int r = 0; r < 4; r++)
            if (r != c) {
                const float f = M[r][c];
                for (int j = 0; j < 8; j++) M[r][j] -= f * M[c][j];
            }
    }
    float* o = g_rt + (b * N_ + v) * 12;
    for (int i = 0; i < 3; i++)
        for (int j = 0; j < 3; j++)
            o[i * 3 + j] = S[i][0] * M[0][4 + j] + S[i][1] * M[1][4 + j] +
                           S[i][2] * M[2][4 + j] + S[i][3] * M[3][4 + j];
    for (int i = 0; i < 3; i++)
        o[9 + i] = S[i][0] * M[0][7] + S[i][1] * M[1][7] + S[i][2] * M[2][7] + S[i][3] * M[3][7];
}

// ---------------------------------------------------------------------------
// Warp per pixel. Per view: phase A stages per-group dot products
// dot_g(p) = sum_{c in g} ref_c*src_c(p)/4 for the epipolar-footprint bbox
// (unique pixels only -> 2.3x fewer L1 bytes); phase B (lane = depth) does
// bilinear over the table in smem. s_g/f_g stay in registers.
// ---------------------------------------------------------------------------
__global__ __launch_bounds__(256) void stage_main(
    const float* __restrict__ regw, const float* __restrict__ regb,
    float* __restrict__ out_depth, float* __restrict__ out_attn) {
    extern __shared__ float sm[];
    const int lane = threadIdx.x & 31;
    const int wi = threadIdx.x >> 5;
    const int x = blockIdx.x * 8 + wi;
    const int y = blockIdx.y;
    const int b = blockIdx.z;
    float* tbl = sm + wi * (CAP * 8);
    float* stg = sm + 8 * (CAP * 8);
    const int pix = y * W_ + x;
    const size_t pb32 = ((size_t)b * HW_ + pix) * 32;

    const int cg = lane & 7;
    const int slot = lane >> 3;
    float4 refv = *(const float4*)(g_ref_t + pb32 + cg * 4);
    refv.x *= 0.25f; refv.y *= 0.25f; refv.z *= 0.25f; refv.w *= 0.25f;
    const float dl = g_dep_t[pb32 + lane];  // lane = depth index

    float f_g[8];
#pragma unroll
    for (int g = 0; g < 8; g++) f_g[g] = 0.f;
    float wsum = 1e-8f;

    const float fx = (float)x, fy = (float)y;

    for (int v = 0; v < N_; v++) {
        const float* rt = g_rt + (b * N_ + v) * 12;
        const float rx = rt[0] * fx + rt[1] * fy + rt[2];
        const float ry = rt[3] * fx + rt[4] * fy + rt[5];
        const float rz = rt[6] * fx + rt[7] * fy + rt[8];
        const float t0 = rt[9], t1 = rt[10], t2 = rt[11];
        const float* sv = g_src_t + ((size_t)(v * B_ + b)) * HW_ * 32;

        // per-lane (lane = depth) coordinates
        float pz = rz * dl + t2;
        pz = (pz == 0.f) ? 1e-9f : pz;
        const float gx = __fdiv_rn(rx * dl + t0, pz);
        const float gy = __fdiv_rn(ry * dl + t1, pz);
        const float x0f = floorf(gx), y0f = floorf(gy);
        const float wx = gx - x0f, wy = gy - y0f;
        const int vx0 = (x0f >= 0.f) & (x0f <= (float)(W_ - 1));
        const int vx1 = (x0f >= -1.f) & (x0f <= (float)(W_ - 2));
        const int vy0 = (y0f >= 0.f) & (y0f <= (float)(H_ - 1));
        const int vy1 = (y0f >= -1.f) & (y0f <= (float)(H_ - 2));
        const int vb = (vx0 & vy0) | ((vx1 & vy0) << 1) | ((vx0 & vy1) << 2) | ((vx1 & vy1) << 3);
        const int ixc = (int)fminf(fmaxf(x0f, -1.f), (float)W_);
        const int iyc = (int)fminf(fmaxf(y0f, -1.f), (float)H_);

        // warp-wide footprint bbox
        const int xmin = __reduce_min_sync(FULLMASK, ixc);
        const int xmax = __reduce_max_sync(FULLMASK, ixc);
        const int ymin = __reduce_min_sync(FULLMASK, iyc);
        const int ymax = __reduce_max_sync(FULLMASK, iyc);
        const int nx = xmax - xmin + 2;
        const int ny = ymax - ymin + 2;

        // valid-masked bilinear weights (0.25 group-mean is baked into refv)
        const float w00 = (1.f - wx) * (1.f - wy) * (float)(vb & 1);
        const float w10 = wx * (1.f - wy) * (float)((vb >> 1) & 1);
        const float w01 = (1.f - wx) * wy * (float)((vb >> 2) & 1);
        const float w11 = wx * wy * (float)((vb >> 3) & 1);

        float s_g[8];
        if (nx * ny <= CAP) {
            // ---- phase A: build per-group dot table over bbox ----
            const float* svc = sv + cg * 4;
            for (int row = 0; row < ny; row++) {
                const int py = min(max(ymin + row, 0), H_ - 1);
                const float* rowp = svc + py * (W_ * 32);
                float* trow = tbl + row * nx * 8;
                for (int c = slot; c < nx; c += 4) {
                    const int px = min(max(xmin + c, 0), W_ - 1);
                    const float4 vv = __ldg((const float4*)(rowp + px * 32));
                    trow[c * 8 + cg] =
                        vv.x * refv.x + vv.y * refv.y + vv.z * refv.z + vv.w * refv.w;
                }
            }
            __syncwarp();
            // ---- phase B: bilinear over table (lane = depth) ----
            const float* t00 = tbl + ((iyc - ymin) * nx + (ixc - xmin)) * 8;
            const float4 a0 = *(const float4*)(t00);
            const float4 a1 = *(const float4*)(t00 + 4);
            const float4 b0 = *(const float4*)(t00 + 8);
            const float4 b1 = *(const float4*)(t00 + 12);
            const float4 c0 = *(const float4*)(t00 + nx * 8);
            const float4 c1 = *(const float4*)(t00 + nx * 8 + 4);
            const float4 d0 = *(const float4*)(t00 + nx * 8 + 8);
            const float4 d1 = *(const float4*)(t00 + nx * 8 + 12);
            s_g[0] = w00 * a0.x + w10 * b0.x + w01 * c0.x + w11 * d0.x;
            s_g[1] = w00 * a0.y + w10 * b0.y + w01 * c0.y + w11 * d0.y;
            s_g[2] = w00 * a0.z + w10 * b0.z + w01 * c0.z + w11 * d0.z;
            s_g[3] = w00 * a0.w + w10 * b0.w + w01 * c0.w + w11 * d0.w;
            s_g[4] = w00 * a1.x + w10 * b1.x + w01 * c1.x + w11 * d1.x;
            s_g[5] = w00 * a1.y + w10 * b1.y + w01 * c1.y + w11 * d1.y;
            s_g[6] = w00 * a1.z + w10 * b1.z + w01 * c1.z + w11 * d1.z;
            s_g[7] = w00 * a1.w + w10 * b1.w + w01 * c1.w + w11 * d1.w;
        } else {
            // ---- fallback (geometry bound says never taken; kept for safety)
#pragma unroll
            for (int g = 0; g < 8; g++) s_g[g] = 0.f;
            const int ix = (int)x0f, iy = (int)y0f;
#pragma unroll
            for (int tap = 0; tap < 4; tap++) {
                if ((vb >> tap) & 1) {
                    const int ttx = tap & 1, tty = tap >> 1;
                    const float wt =
                        (ttx ? wx : 1.f - wx) * (tty ? wy : 1.f - wy) * 0.25f;
                    const float* pp = sv + ((size_t)(iy + tty) * W_ + (ix + ttx)) * 32;
#pragma unroll
                    for (int g = 0; g < 8; g++) {
                        const float4 vv = __ldg((const float4*)(pp + g * 4));
                        const float4 rr = __ldg((const float4*)(g_ref_t + pb32 + g * 4));
                        s_g[g] += wt * (vv.x * rr.x + vv.y * rr.y + vv.z * rr.z + vv.w * rr.w);
                    }
                }
            }
        }

        // per-view softmax over depth (lane = depth, all registers)
        float logit = s_g[0] + s_g[1] + s_g[2] + s_g[3] + s_g[4] + s_g[5] + s_g[6] + s_g[7];
        logit *= 0.5f;
        float mx = logit;
#pragma unroll
        for (int o = 16; o > 0; o >>= 1) mx = fmaxf(mx, __shfl_xor_sync(FULLMASK, mx, o));
        const float e = expf(logit - mx);
        float tot = e;
#pragma unroll
        for (int o = 16; o > 0; o >>= 1) tot += __shfl_xor_sync(FULLMASK, tot, o);
        const float w = __fdiv_rn(e, tot) * 0.17677669529663687f;  // / sqrt(C)
        wsum += w;
#pragma unroll
        for (int g = 0; g < 8; g++) f_g[g] += w * s_g[g];
        __syncwarp();  // table reads done before next view overwrites
    }

    // Final regression + softmax + argmax (lane = depth)
    float acc = 0.f;
#pragma unroll
    for (int g = 0; g < 8; g++) acc += f_g[g] * __ldg(regw + g);
    const float logit = __fdiv_rn(acc, wsum) + __ldg(regb);
    float mx = logit;
#pragma unroll
    for (int o = 16; o > 0; o >>= 1) mx = fmaxf(mx, __shfl_xor_sync(FULLMASK, mx, o));
    const float e = expf(logit - mx);
    float tot = e;
#pragma unroll
    for (int o = 16; o > 0; o >>= 1) tot += __shfl_xor_sync(FULLMASK, tot, o);
    const float attn = __fdiv_rn(e, tot);

    float bv = attn;
    int bi = lane;
#pragma unroll
    for (int o = 16; o > 0; o >>= 1) {
        const float ov = __shfl_xor_sync(FULLMASK, bv, o);
        const int oi = __shfl_xor_sync(FULLMASK, bi, o);
        if (ov > bv || (ov == bv && oi < bi)) { bv = ov; bi = oi; }
    }
    const float dsel = __shfl_sync(FULLMASK, dl, bi);
    if (lane == 0) out_depth[(b * H_ + y) * W_ + x] = dsel;

    stg[wi * 32 + lane] = attn;
    __syncthreads();
    const int t = threadIdx.x;
    const int dd = t >> 3, wj = t & 7;
    out_attn[(((size_t)b * D_ + dd) * H_ + y) * W_ + blockIdx.x * 8 + wj] =
        stg[wj * 32 + dd];
}

// ---------------------------------------------------------------------------
extern "C" void kernel_launch(void* const* d_in, const int* in_sizes, int n_in,
                              void* d_out, int out_size) {
    const float* ref = (const float*)d_in[0];
    const float* src = (const float*)d_in[1];
    const float* pm  = (const float*)d_in[2];
    const float* dep = (const float*)d_in[3];
    const float* rw  = (const float*)d_in[4];
    const float* rb  = (const float*)d_in[5];
    float* out_depth = (float*)d_out;
    float* out_attn  = out_depth + (size_t)B_ * HW_;

    float *g_src_p, *g_ref_p, *g_dep_p;
    cudaGetSymbolAddress((void**)&g_src_p, g_src_t);
    cudaGetSymbolAddress((void**)&g_ref_p, g_ref_t);
    cudaGetSymbolAddress((void**)&g_dep_p, g_dep_t);

    const int smem_bytes = SMEM_FLOATS * (int)sizeof(float);
    cudaFuncSetAttribute(stage_main, cudaFuncAttributeMaxDynamicSharedMemorySize,
                         smem_bytes);

    dim3 tb(32, 8);
    transpose_c32<<<dim3(HW_ / 32, 1, N_ * B_), tb>>>(src, g_src_p);
    transpose_c32<<<dim3(HW_ / 32, 1, B_), tb>>>(ref, g_ref_p);
    transpose_c32<<<dim3(HW_ / 32, 1, B_), tb>>>(dep, g_dep_p);
    setup_proj<<<1, 32>>>(pm);
    stage_main<<<dim3(W_ / 8, H_, B_), 256, smem_bytes>>>(rw, rb, out_depth, out_attn);
}

// round 7
// speedup vs baseline: 1.2103x; 1.2103x over previous
#include <cuda_runtime.h>
#include <cstdint>
#include <math.h>

namespace {
constexpr int B_ = 2;
constexpr int C_ = 32;
constexpr int H_ = 128;
constexpr int W_ = 160;
constexpr int D_ = 32;
constexpr int N_ = 4;
constexpr int HW_ = H_ * W_;
}

#define FULLMASK 0xffffffffu

__device__ float g_src_t[N_ * B_ * HW_ * C_];  // [v][b][pix][c]
__device__ float g_ref_t[B_ * HW_ * C_];       // [b][pix][c]
__device__ float g_dep_t[B_ * HW_ * D_];       // [b][pix][d]
__device__ float g_rt[B_ * N_ * 12];           // rot(9) + trans(3)

// ---------------------------------------------------------------------------
__global__ void transpose_c32(const float* __restrict__ in, float* __restrict__ out) {
    __shared__ float tile[32][33];
    const int p = blockIdx.z;
    const int hw0 = blockIdx.x * 32;
    const float* ip = in + (size_t)p * 32 * HW_;
    float* op = out + (size_t)p * HW_ * 32;
    const int tx = threadIdx.x, ty = threadIdx.y;
#pragma unroll
    for (int k = 0; k < 32; k += 8)
        tile[ty + k][tx] = ip[(size_t)(ty + k) * HW_ + hw0 + tx];
    __syncthreads();
#pragma unroll
    for (int k = 0; k < 32; k += 8)
        op[(size_t)(hw0 + ty + k) * 32 + tx] = tile[tx][ty + k];
}

// ---------------------------------------------------------------------------
__device__ void build_new(const float* pm, int b, int vv, float Mo[4][4]) {
    const float* E = pm + (((b * (N_ + 1) + vv) * 2 + 0) * 16);
    const float* K = pm + (((b * (N_ + 1) + vv) * 2 + 1) * 16);
    for (int i = 0; i < 3; i++)
        for (int j = 0; j < 4; j++)
            Mo[i][j] = K[i * 4 + 0] * E[0 + j] + K[i * 4 + 1] * E[4 + j] + K[i * 4 + 2] * E[8 + j];
    for (int j = 0; j < 4; j++) Mo[3][j] = E[12 + j];
}

__global__ void setup_proj(const float* __restrict__ pm) {
    const int t = threadIdx.x;
    if (t >= B_ * N_) return;
    const int b = t / N_, v = t % N_;
    float R[4][4], S[4][4];
    build_new(pm, b, 0, R);
    build_new(pm, b, v + 1, S);
    float M[4][8];
    for (int i = 0; i < 4; i++)
        for (int j = 0; j < 4; j++) { M[i][j] = R[i][j]; M[i][4 + j] = (i == j) ? 1.f : 0.f; }
    for (int c = 0; c < 4; c++) {
        int piv = c;
        for (int r = c + 1; r < 4; r++)
            if (fabsf(M[r][c]) > fabsf(M[piv][c])) piv = r;
        if (piv != c)
            for (int j = 0; j < 8; j++) { float tmp = M[c][j]; M[c][j] = M[piv][j]; M[piv][j] = tmp; }
        const float ip = 1.f / M[c][c];
        for (int j = 0; j < 8; j++) M[c][j] *= ip;
        for (int r = 0; r < 4; r++)
            if (r != c) {
                const float f = M[r][c];
                for (int j = 0; j < 8; j++) M[r][j] -= f * M[c][j];
            }
    }
    float* o = g_rt + (b * N_ + v) * 12;
    for (int i = 0; i < 3; i++)
        for (int j = 0; j < 3; j++)
            o[i * 3 + j] = S[i][0] * M[0][4 + j] + S[i][1] * M[1][4 + j] +
                           S[i][2] * M[2][4 + j] + S[i][3] * M[3][4 + j];
    for (int i = 0; i < 3; i++)
        o[9 + i] = S[i][0] * M[0][7] + S[i][1] * M[1][7] + S[i][2] * M[2][7] + S[i][3] * M[3][7];
}

// ---------------------------------------------------------------------------
// Warp per pixel. Direct branch-free gather (R5 tap scheme), but with:
//  - all 4 views' coordinates precomputed up front (divs pipelined once),
//  - 4 back-to-back gather loops into 4 per-warp smem buffers (no drains),
//  - single deferred epilogue, f_g/wsum in registers, fast softmax math.
// Lane: cg=lane&7 (4-ch group), tx=(lane>>3)&1, ty=lane>>4 (tap corner).
// pk packs: vb(4b) | ix+1 (8b) | iy+1 (rest).
// ---------------------------------------------------------------------------
__global__ __launch_bounds__(256, 3) void stage_main(
    const float* __restrict__ regw, const float* __restrict__ regb,
    float* __restrict__ out_depth, float* __restrict__ out_attn) {
    __shared__ float sm[8 * 1056 + 256];
    const int lane = threadIdx.x & 31;
    const int wi = threadIdx.x >> 5;
    const int x = blockIdx.x * 8 + wi;
    const int y = blockIdx.y;
    const int b = blockIdx.z;
    float* s4 = sm + wi * 1056;      // 4 views x s[g*33 + d]
    float* stg = sm + 8 * 1056;      // attn staging
    const int pix = y * W_ + x;
    const size_t pb32 = ((size_t)b * HW_ + pix) * 32;

    const int cg = lane & 7;
    const int tx = (lane >> 3) & 1;
    const int ty = lane >> 4;
    const int tapbit = tx + 2 * ty;
    const int xadd = tx - 1;
    const int yadd = ty - 1;
    float4 refv = *(const float4*)(g_ref_t + pb32 + cg * 4);
    refv.x *= 0.25f; refv.y *= 0.25f; refv.z *= 0.25f; refv.w *= 0.25f;
    const float dl = g_dep_t[pb32 + lane];  // lane = depth index
    const float fx = (float)x, fy = (float)y;

    // ---- coordinates for all views, up front (lane = depth) ----
    int pkA[N_];
    float wxA[N_], wyA[N_];
#pragma unroll
    for (int v = 0; v < N_; v++) {
        const float* rt = g_rt + (b * N_ + v) * 12;
        const float rx = rt[0] * fx + rt[1] * fy + rt[2];
        const float ry = rt[3] * fx + rt[4] * fy + rt[5];
        const float rz = rt[6] * fx + rt[7] * fy + rt[8];
        float pz = rz * dl + rt[11];
        pz = (pz == 0.f) ? 1e-9f : pz;
        const float gx = __fdiv_rn(rx * dl + rt[9], pz);
        const float gy = __fdiv_rn(ry * dl + rt[10], pz);
        const float x0f = floorf(gx), y0f = floorf(gy);
        wxA[v] = gx - x0f;
        wyA[v] = gy - y0f;
        const int vx0 = (x0f >= 0.f) & (x0f <= (float)(W_ - 1));
        const int vx1 = (x0f >= -1.f) & (x0f <= (float)(W_ - 2));
        const int vy0 = (y0f >= 0.f) & (y0f <= (float)(H_ - 1));
        const int vy1 = (y0f >= -1.f) & (y0f <= (float)(H_ - 2));
        const int vb = (vx0 & vy0) | ((vx1 & vy0) << 1) | ((vx0 & vy1) << 2) | ((vx1 & vy1) << 3);
        const int ixp = (int)fminf(fmaxf(x0f, -1.f), (float)W_) + 1;
        const int iyp = (int)fminf(fmaxf(y0f, -1.f), (float)H_) + 1;
        pkA[v] = vb | (ixp << 4) | (iyp << 12);
    }

    // ---- one uninterrupted gather stream over all 4 views ----
#pragma unroll
    for (int v = 0; v < N_; v++) {
        const float* sv = g_src_t + ((size_t)(v * B_ + b)) * HW_ * 32 + cg * 4;
        float* ss = s4 + v * 264;
#pragma unroll 8
        for (int d = 0; d < D_; d++) {
            const int pkd = __shfl_sync(FULLMASK, pkA[v], d);
            const float wx = __shfl_sync(FULLMASK, wxA[v], d);
            const float wy = __shfl_sync(FULLMASK, wyA[v], d);
            const int px = min(max(((pkd >> 4) & 0xff) + xadd, 0), W_ - 1);
            const int py = min(max((pkd >> 12) + yadd, 0), H_ - 1);
            const float4 vv = __ldg((const float4*)(sv + (py * W_ + px) * 32));
            const float valid = (float)((pkd >> tapbit) & 1);
            const float wt = (tx ? wx : 1.f - wx) * (ty ? wy : 1.f - wy) * valid;
            float pr = wt * (vv.x * refv.x + vv.y * refv.y + vv.z * refv.z + vv.w * refv.w);
            pr += __shfl_xor_sync(FULLMASK, pr, 8);
            pr += __shfl_xor_sync(FULLMASK, pr, 16);
            if (lane < 8) ss[lane * 33 + d] = pr;
        }
    }
    __syncwarp();

    // ---- deferred epilogue: per-view softmax + register accumulation ----
    float f_g[8];
#pragma unroll
    for (int g = 0; g < 8; g++) f_g[g] = 0.f;
    float wsum = 1e-8f;

#pragma unroll
    for (int v = 0; v < N_; v++) {
        float sg[8];
#pragma unroll
        for (int g = 0; g < 8; g++) sg[g] = s4[v * 264 + g * 33 + lane];
        float logit = ((sg[0] + sg[1]) + (sg[2] + sg[3])) +
                      ((sg[4] + sg[5]) + (sg[6] + sg[7]));
        logit *= 0.5f;
        float mx = logit;
#pragma unroll
        for (int o = 16; o > 0; o >>= 1) mx = fmaxf(mx, __shfl_xor_sync(FULLMASK, mx, o));
        const float e = __expf(logit - mx);
        float tot = e;
#pragma unroll
        for (int o = 16; o > 0; o >>= 1) tot += __shfl_xor_sync(FULLMASK, tot, o);
        const float w = __fdividef(e, tot) * 0.17677669529663687f;  // / sqrt(C)
        wsum += w;
#pragma unroll
        for (int g = 0; g < 8; g++) f_g[g] += w * sg[g];
    }

    // Final regression + softmax + argmax (lane = depth)
    float acc = 0.f;
#pragma unroll
    for (int g = 0; g < 8; g++) acc += f_g[g] * __ldg(regw + g);
    const float logit = __fdiv_rn(acc, wsum) + __ldg(regb);
    float mx = logit;
#pragma unroll
    for (int o = 16; o > 0; o >>= 1) mx = fmaxf(mx, __shfl_xor_sync(FULLMASK, mx, o));
    const float e = __expf(logit - mx);
    float tot = e;
#pragma unroll
    for (int o = 16; o > 0; o >>= 1) tot += __shfl_xor_sync(FULLMASK, tot, o);
    const float attn = __fdividef(e, tot);

    float bv = attn;
    int bi = lane;
#pragma unroll
    for (int o = 16; o > 0; o >>= 1) {
        const float ov = __shfl_xor_sync(FULLMASK, bv, o);
        const int oi = __shfl_xor_sync(FULLMASK, bi, o);
        if (ov > bv || (ov == bv && oi < bi)) { bv = ov; bi = oi; }
    }
    const float dsel = __shfl_sync(FULLMASK, dl, bi);
    if (lane == 0) out_depth[(b * H_ + y) * W_ + x] = dsel;

    stg[wi * 32 + lane] = attn;
    __syncthreads();
    const int t = threadIdx.x;
    const int dd = t >> 3, wj = t & 7;
    out_attn[(((size_t)b * D_ + dd) * H_ + y) * W_ + blockIdx.x * 8 + wj] =
        stg[wj * 32 + dd];
}

// ---------------------------------------------------------------------------
extern "C" void kernel_launch(void* const* d_in, const int* in_sizes, int n_in,
                              void* d_out, int out_size) {
    const float* ref = (const float*)d_in[0];
    const float* src = (const float*)d_in[1];
    const float* pm  = (const float*)d_in[2];
    const float* dep = (const float*)d_in[3];
    const float* rw  = (const float*)d_in[4];
    const float* rb  = (const float*)d_in[5];
    float* out_depth = (float*)d_out;
    float* out_attn  = out_depth + (size_t)B_ * HW_;

    float *g_src_p, *g_ref_p, *g_dep_p;
    cudaGetSymbolAddress((void**)&g_src_p, g_src_t);
    cudaGetSymbolAddress((void**)&g_ref_p, g_ref_t);
    cudaGetSymbolAddress((void**)&g_dep_p, g_dep_t);

    dim3 tb(32, 8);
    transpose_c32<<<dim3(HW_ / 32, 1, N_ * B_), tb>>>(src, g_src_p);
    transpose_c32<<<dim3(HW_ / 32, 1, B_), tb>>>(ref, g_ref_p);
    transpose_c32<<<dim3(HW_ / 32, 1, B_), tb>>>(dep, g_dep_p);
    setup_proj<<<1, 32>>>(pm);
    stage_main<<<dim3(W_ / 8, H_, B_), 256>>>(rw, rb, out_depth, out_attn);
}

// round 9
// speedup vs baseline: 1.2632x; 1.0437x over previous
#include <cuda_runtime.h>
#include <cstdint>
#include <math.h>

namespace {
constexpr int B_ = 2;
constexpr int C_ = 32;
constexpr int H_ = 128;
constexpr int W_ = 160;
constexpr int D_ = 32;
constexpr int N_ = 4;
constexpr int HW_ = H_ * W_;
}

#define FULLMASK 0xffffffffu

__device__ float g_src_t[N_ * B_ * HW_ * C_];  // [v][b][pix][c]
__device__ float g_ref_t[B_ * HW_ * C_];       // [b][pix][c]
__device__ float g_dep_t[B_ * HW_ * D_];       // [b][pix][d]
__device__ float g_rt[B_ * N_ * 12];           // rot(9) + trans(3)

// ---------------------------------------------------------------------------
// Fused transpose: all 12 planes ([P][32][HW] -> [P][HW][32]) in ONE launch.
// z 0..7 = src views, 8..9 = ref, 10..11 = depth.
// ---------------------------------------------------------------------------
__global__ void transpose_all(const float* __restrict__ src,
                              const float* __restrict__ ref,
                              const float* __restrict__ dep,
                              float* __restrict__ osrc,
                              float* __restrict__ oref,
                              float* __restrict__ odep) {
    __shared__ float tile[32][33];
    const int z = blockIdx.z;
    const float* ip;
    float* op;
    if (z < 8) {
        ip = src + (size_t)z * 32 * HW_;
        op = osrc + (size_t)z * HW_ * 32;
    } else if (z < 10) {
        ip = ref + (size_t)(z - 8) * 32 * HW_;
        op = oref + (size_t)(z - 8) * HW_ * 32;
    } else {
        ip = dep + (size_t)(z - 10) * 32 * HW_;
        op = odep + (size_t)(z - 10) * HW_ * 32;
    }
    const int hw0 = blockIdx.x * 32;
    const int tx = threadIdx.x, ty = threadIdx.y;
#pragma unroll
    for (int k = 0; k < 32; k += 8)
        tile[ty + k][tx] = ip[(size_t)(ty + k) * HW_ + hw0 + tx];
    __syncthreads();
#pragma unroll
    for (int k = 0; k < 32; k += 8)
        op[(size_t)(hw0 + ty + k) * 32 + tx] = tile[tx][ty + k];
}

// ---------------------------------------------------------------------------
__device__ void build_new(const float* pm, int b, int vv, float Mo[4][4]) {
    const float* E = pm + (((b * (N_ + 1) + vv) * 2 + 0) * 16);
    const float* K = pm + (((b * (N_ + 1) + vv) * 2 + 1) * 16);
    for (int i = 0; i < 3; i++)
        for (int j = 0; j < 4; j++)
            Mo[i][j] = K[i * 4 + 0] * E[0 + j] + K[i * 4 + 1] * E[4 + j] + K[i * 4 + 2] * E[8 + j];
    for (int j = 0; j < 4; j++) Mo[3][j] = E[12 + j];
}

__global__ void setup_proj(const float* __restrict__ pm) {
    const int t = threadIdx.x;
    if (t >= B_ * N_) return;
    const int b = t / N_, v = t % N_;
    float R[4][4], S[4][4];
    build_new(pm, b, 0, R);
    build_new(pm, b, v + 1, S);
    float M[4][8];
    for (int i = 0; i < 4; i++)
        for (int j = 0; j < 4; j++) { M[i][j] = R[i][j]; M[i][4 + j] = (i == j) ? 1.f : 0.f; }
    for (int c = 0; c < 4; c++) {
        int piv = c;
        for (int r = c + 1; r < 4; r++)
            if (fabsf(M[r][c]) > fabsf(M[piv][c])) piv = r;
        if (piv != c)
            for (int j = 0; j < 8; j++) { float tmp = M[c][j]; M[c][j] = M[piv][j]; M[piv][j] = tmp; }
        const float ip = 1.f / M[c][c];
        for (int j = 0; j < 8; j++) M[c][j] *= ip;
        for (int r = 0; r < 4; r++)
            if (r != c) {
                const float f = M[r][c];
                for (int j = 0; j < 8; j++) M[r][j] -= f * M[c][j];
            }
    }
    float* o = g_rt + (b * N_ + v) * 12;
    for (int i = 0; i < 3; i++)
        for (int j = 0; j < 3; j++)
            o[i * 3 + j] = S[i][0] * M[0][4 + j] + S[i][1] * M[1][4 + j] +
                           S[i][2] * M[2][4 + j] + S[i][3] * M[3][4 + j];
    for (int i = 0; i < 3; i++)
        o[9 + i] = S[i][0] * M[0][7] + S[i][1] * M[1][7] + S[i][2] * M[2][7] + S[i][3] * M[3][7];
}

// ---------------------------------------------------------------------------
// Warp per pixel, fp32 direct gather (R7 body), occupancy pushed to 4 blocks.
// Lane: cg=lane&7 (4-ch group), tx=(lane>>3)&1, ty=lane>>4 (tap corner).
// pk packs: vb(4b) | ix+1 (8b) | iy+1 (rest).
// ---------------------------------------------------------------------------
__global__ __launch_bounds__(256, 4) void stage_main(
    const float* __restrict__ regw, const float* __restrict__ regb,
    float* __restrict__ out_depth, float* __restrict__ out_attn) {
    __shared__ float sm[8 * 1056 + 256];
    const int lane = threadIdx.x & 31;
    const int wi = threadIdx.x >> 5;
    const int x = blockIdx.x * 8 + wi;
    const int y = blockIdx.y;
    const int b = blockIdx.z;
    float* s4 = sm + wi * 1056;      // 4 views x s[g*33 + d]
    float* stg = sm + 8 * 1056;      // attn staging
    const int pix = y * W_ + x;
    const size_t pb32 = ((size_t)b * HW_ + pix) * 32;

    const int cg = lane & 7;
    const int tx = (lane >> 3) & 1;
    const int ty = lane >> 4;
    const int tapbit = tx + 2 * ty;
    const int xadd = tx - 1;
    const int yadd = ty - 1;
    float4 refv = *(const float4*)(g_ref_t + pb32 + cg * 4);
    refv.x *= 0.25f; refv.y *= 0.25f; refv.z *= 0.25f; refv.w *= 0.25f;
    const float dl = g_dep_t[pb32 + lane];  // lane = depth index
    const float fx = (float)x, fy = (float)y;

    // ---- coordinates for all views, up front (lane = depth) ----
    int pkA[N_];
    float wxA[N_], wyA[N_];
#pragma unroll
    for (int v = 0; v < N_; v++) {
        const float* rt = g_rt + (b * N_ + v) * 12;
        const float rx = rt[0] * fx + rt[1] * fy + rt[2];
        const float ry = rt[3] * fx + rt[4] * fy + rt[5];
        const float rz = rt[6] * fx + rt[7] * fy + rt[8];
        float pz = rz * dl + rt[11];
        pz = (pz == 0.f) ? 1e-9f : pz;
        const float gx = __fdiv_rn(rx * dl + rt[9], pz);
        const float gy = __fdiv_rn(ry * dl + rt[10], pz);
        const float x0f = floorf(gx), y0f = floorf(gy);
        wxA[v] = gx - x0f;
        wyA[v] = gy - y0f;
        const int vx0 = (x0f >= 0.f) & (x0f <= (float)(W_ - 1));
        const int vx1 = (x0f >= -1.f) & (x0f <= (float)(W_ - 2));
        const int vy0 = (y0f >= 0.f) & (y0f <= (float)(H_ - 1));
        const int vy1 = (y0f >= -1.f) & (y0f <= (float)(H_ - 2));
        const int vb = (vx0 & vy0) | ((vx1 & vy0) << 1) | ((vx0 & vy1) << 2) | ((vx1 & vy1) << 3);
        const int ixp = (int)fminf(fmaxf(x0f, -1.f), (float)W_) + 1;
        const int iyp = (int)fminf(fmaxf(y0f, -1.f), (float)H_) + 1;
        pkA[v] = vb | (ixp << 4) | (iyp << 12);
    }

    // ---- one uninterrupted gather stream over all 4 views ----
#pragma unroll
    for (int v = 0; v < N_; v++) {
        const float* sv = g_src_t + ((size_t)(v * B_ + b)) * HW_ * 32 + cg * 4;
        float* ss = s4 + v * 264;
#pragma unroll 8
        for (int d = 0; d < D_; d++) {
            const int pkd = __shfl_sync(FULLMASK, pkA[v], d);
            const float wx = __shfl_sync(FULLMASK, wxA[v], d);
            const float wy = __shfl_sync(FULLMASK, wyA[v], d);
            const int px = min(max(((pkd >> 4) & 0xff) + xadd, 0), W_ - 1);
            const int py = min(max((pkd >> 12) + yadd, 0), H_ - 1);
            const float4 vv = __ldg((const float4*)(sv + (py * W_ + px) * 32));
            const float valid = (float)((pkd >> tapbit) & 1);
            const float wt = (tx ? wx : 1.f - wx) * (ty ? wy : 1.f - wy) * valid;
            float pr = wt * (vv.x * refv.x + vv.y * refv.y + vv.z * refv.z + vv.w * refv.w);
            pr += __shfl_xor_sync(FULLMASK, pr, 8);
            pr += __shfl_xor_sync(FULLMASK, pr, 16);
            if (lane < 8) ss[lane * 33 + d] = pr;
        }
    }
    __syncwarp();

    // ---- deferred epilogue: per-view softmax + register accumulation ----
    float f_g[8];
#pragma unroll
    for (int g = 0; g < 8; g++) f_g[g] = 0.f;
    float wsum = 1e-8f;

#pragma unroll
    for (int v = 0; v < N_; v++) {
        float sg[8];
#pragma unroll
        for (int g = 0; g < 8; g++) sg[g] = s4[v * 264 + g * 33 + lane];
        float logit = ((sg[0] + sg[1]) + (sg[2] + sg[3])) +
                      ((sg[4] + sg[5]) + (sg[6] + sg[7]));
        logit *= 0.5f;
        float mx = logit;
#pragma unroll
        for (int o = 16; o > 0; o >>= 1) mx = fmaxf(mx, __shfl_xor_sync(FULLMASK, mx, o));
        const float e = __expf(logit - mx);
        float tot = e;
#pragma unroll
        for (int o = 16; o > 0; o >>= 1) tot += __shfl_xor_sync(FULLMASK, tot, o);
        const float w = __fdividef(e, tot) * 0.17677669529663687f;  // / sqrt(C)
        wsum += w;
#pragma unroll
        for (int g = 0; g < 8; g++) f_g[g] += w * sg[g];
    }

    // Final regression + softmax + argmax (lane = depth)
    float acc = 0.f;
#pragma unroll
    for (int g = 0; g < 8; g++) acc += f_g[g] * __ldg(regw + g);
    const float logit = __fdiv_rn(acc, wsum) + __ldg(regb);
    float mx = logit;
#pragma unroll
    for (int o = 16; o > 0; o >>= 1) mx = fmaxf(mx, __shfl_xor_sync(FULLMASK, mx, o));
    const float e = __expf(logit - mx);
    float tot = e;
#pragma unroll
    for (int o = 16; o > 0; o >>= 1) tot += __shfl_xor_sync(FULLMASK, tot, o);
    const float attn = __fdividef(e, tot);

    float bv = attn;
    int bi = lane;
#pragma unroll
    for (int o = 16; o > 0; o >>= 1) {
        const float ov = __shfl_xor_sync(FULLMASK, bv, o);
        const int oi = __shfl_xor_sync(FULLMASK, bi, o);
        if (ov > bv || (ov == bv && oi < bi)) { bv = ov; bi = oi; }
    }
    const float dsel = __shfl_sync(FULLMASK, dl, bi);
    if (lane == 0) out_depth[(b * H_ + y) * W_ + x] = dsel;

    stg[wi * 32 + lane] = attn;
    __syncthreads();
    const int t = threadIdx.x;
    const int dd = t >> 3, wj = t & 7;
    out_attn[(((size_t)b * D_ + dd) * H_ + y) * W_ + blockIdx.x * 8 + wj] =
        stg[wj * 32 + dd];
}

// ---------------------------------------------------------------------------
extern "C" void kernel_launch(void* const* d_in, const int* in_sizes, int n_in,
                              void* d_out, int out_size) {
    const float* ref = (const float*)d_in[0];
    const float* src = (const float*)d_in[1];
    const float* pm  = (const float*)d_in[2];
    const float* dep = (const float*)d_in[3];
    const float* rw  = (const float*)d_in[4];
    const float* rb  = (const float*)d_in[5];
    float* out_depth = (float*)d_out;
    float* out_attn  = out_depth + (size_t)B_ * HW_;

    float *g_src_p, *g_ref_p, *g_dep_p;
    cudaGetSymbolAddress((void**)&g_src_p, g_src_t);
    cudaGetSymbolAddress((void**)&g_ref_p, g_ref_t);
    cudaGetSymbolAddress((void**)&g_dep_p, g_dep_t);

    dim3 tb(32, 8);
    transpose_all<<<dim3(HW_ / 32, 1, 12), tb>>>(src, ref, dep, g_src_p, g_ref_p, g_dep_p);
    setup_proj<<<1, 32>>>(pm);
    stage_main<<<dim3(W_ / 8, H_, B_), 256>>>(rw, rb, out_depth, out_attn);
}